// round 3
// baseline (speedup 1.0000x reference)
#include <cuda_runtime.h>
#include <cstdint>
#include <cstddef>

#define SEQ 4096
#define HID 256
#define NHEAD 6
#define H3 768

// ---------------- scratch (static device globals; no allocation) ----------------
__device__ float g_x[SEQ * HID];                       // embedded tokens
__device__ float g_q[NHEAD * SEQ * HID];
__device__ float g_k[NHEAD * SEQ * HID];
__device__ float g_v[NHEAD * SEQ * HID];
__device__ float g_sc[(size_t)NHEAD * SEQ * SEQ];      // attention scores (402 MB)
__device__ float g_o[NHEAD * SEQ * HID];
__device__ float g_cat[(size_t)SEQ * NHEAD * HID];
__device__ float g_p[SEQ * HID];                       // attn output proj
__device__ float g_y[SEQ * HID];                       // post-LayerNorm
__device__ float g_gi[SEQ * H3];                       // precomputed GRU input gates

// ---------------- embedding gather ----------------
__global__ void k_embed(const int* __restrict__ tok, const float* __restrict__ emb) {
    int s = blockIdx.x, t = threadIdx.x;
    g_x[s * HID + t] = emb[(size_t)tok[s] * HID + t];
}

// ---------------- generic tiled SGEMM: C = alpha * A@B(^T) (+ bias[n]) ----------------
// 64x64 tile, KS=16, 256 threads, 4x4 micro-tile. All dims multiples of 64/16 here.
template <bool TB, bool HASBIAS>
__global__ void sgemm64(const float* __restrict__ A, const float* __restrict__ B,
                        const float* __restrict__ bias, float* __restrict__ C,
                        int M, int N, int K, float alpha,
                        size_t aB, size_t bB, size_t biasB, size_t cB) {
    A += (size_t)blockIdx.z * aB;
    B += (size_t)blockIdx.z * bB;
    C += (size_t)blockIdx.z * cB;
    if (HASBIAS) bias += (size_t)blockIdx.z * biasB;

    __shared__ float As[16][65];
    __shared__ float Bs[16][65];

    int tid = threadIdx.x;
    int tx = tid & 15, ty = tid >> 4;
    int m0 = blockIdx.y * 64, n0 = blockIdx.x * 64;

    float acc[4][4] = {};

    for (int k0 = 0; k0 < K; k0 += 16) {
        // load A tile: 64 rows x 16 k, coalesced along k
        #pragma unroll
        for (int r = 0; r < 4; r++) {
            int idx = tid + r * 256;
            int mm = idx >> 4;
            int kk = idx & 15;
            As[kk][mm] = A[(size_t)(m0 + mm) * K + k0 + kk];
        }
        // load B tile
        #pragma unroll
        for (int r = 0; r < 4; r++) {
            int idx = tid + r * 256;
            if (!TB) {
                int kk = idx >> 6;
                int nn = idx & 63;
                Bs[kk][nn] = B[(size_t)(k0 + kk) * N + n0 + nn];
            } else {
                int nn = idx >> 4;
                int kk = idx & 15;
                Bs[kk][nn] = B[(size_t)(n0 + nn) * K + k0 + kk];
            }
        }
        __syncthreads();
        #pragma unroll
        for (int kk = 0; kk < 16; kk++) {
            float a[4], b[4];
            #pragma unroll
            for (int i = 0; i < 4; i++) a[i] = As[kk][ty + 16 * i];
            #pragma unroll
            for (int j = 0; j < 4; j++) b[j] = Bs[kk][tx + 16 * j];
            #pragma unroll
            for (int i = 0; i < 4; i++)
                #pragma unroll
                for (int j = 0; j < 4; j++) acc[i][j] += a[i] * b[j];
        }
        __syncthreads();
    }

    #pragma unroll
    for (int i = 0; i < 4; i++) {
        int m = m0 + ty + 16 * i;
        #pragma unroll
        for (int j = 0; j < 4; j++) {
            int n = n0 + tx + 16 * j;
            float vv = acc[i][j] * alpha;
            if (HASBIAS) vv += bias[n];
            C[(size_t)m * N + n] = vv;
        }
    }
}

// ---------------- row softmax over 4096-length rows ----------------
__global__ void k_softmax(float* __restrict__ sc) {
    float* row = sc + (size_t)blockIdx.x * SEQ;
    int t = threadIdx.x;  // 256
    float v[16];
    float mx = -1e30f;
    #pragma unroll
    for (int i = 0; i < 16; i++) { v[i] = row[t + 256 * i]; mx = fmaxf(mx, v[i]); }
    __shared__ float red[256];
    red[t] = mx; __syncthreads();
    for (int s = 128; s > 0; s >>= 1) { if (t < s) red[t] = fmaxf(red[t], red[t + s]); __syncthreads(); }
    mx = red[0]; __syncthreads();
    float sum = 0.f;
    #pragma unroll
    for (int i = 0; i < 16; i++) { v[i] = __expf(v[i] - mx); sum += v[i]; }
    red[t] = sum; __syncthreads();
    for (int s = 128; s > 0; s >>= 1) { if (t < s) red[t] += red[t + s]; __syncthreads(); }
    float inv = 1.0f / red[0];
    #pragma unroll
    for (int i = 0; i < 16; i++) row[t + 256 * i] = v[i] * inv;
}

// ---------------- concat heads: cat[s, h*H + d] = o[h, s, d] ----------------
__global__ void k_cat() {
    int b = blockIdx.x;              // NHEAD*SEQ blocks
    int h = b >> 12;                 // / SEQ
    int s = b & (SEQ - 1);
    int t = threadIdx.x;
    g_cat[(size_t)s * (NHEAD * HID) + h * HID + t] = g_o[((size_t)h * SEQ + s) * HID + t];
}

// ---------------- residual + LayerNorm ----------------
__global__ void k_addln(const float* __restrict__ g, const float* __restrict__ b) {
    int s = blockIdx.x, t = threadIdx.x;
    float v = g_x[s * HID + t] + g_p[s * HID + t];
    __shared__ float r1[256], r2[256];
    r1[t] = v; r2[t] = v * v; __syncthreads();
    for (int st = 128; st > 0; st >>= 1) {
        if (t < st) { r1[t] += r1[t + st]; r2[t] += r2[t + st]; }
        __syncthreads();
    }
    float mu = r1[0] * (1.0f / HID);
    float var = r2[0] * (1.0f / HID) - mu * mu;
    g_y[s * HID + t] = (v - mu) * rsqrtf(var + 1e-5f) * g[t] + b[t];
}

// ---------------- GRU: 8-CTA cluster, W_hh register-resident ----------------
__device__ __forceinline__ void cluster_sync_() {
    asm volatile("barrier.cluster.arrive.aligned;" ::: "memory");
    asm volatile("barrier.cluster.wait.aligned;" ::: "memory");
}
__device__ __forceinline__ uint32_t smem_u32_(const void* p) {
    uint32_t a;
    asm("{ .reg .u64 t; cvta.to.shared.u64 t, %1; cvt.u32.u64 %0, t; }" : "=r"(a) : "l"(p));
    return a;
}

__global__ void __cluster_dims__(8, 1, 1) __launch_bounds__(512, 1)
k_gru(const float* __restrict__ gi, const float* __restrict__ W_hh,
      const float* __restrict__ b_hh, float* __restrict__ out, int out_size) {
    __shared__ __align__(16) float h_s[2][HID];
    __shared__ float gh_s[96];
    __shared__ float gi_s[2][96];

    uint32_t rank;
    asm("mov.u32 %0, %%cluster_ctarank;" : "=r"(rank));
    int tid = threadIdx.x;
    int w = tid >> 5, l = tid & 31;

    // CTA `rank` owns h-dims [32*rank, 32*rank+32): 96 rows of W_hh (r,z,n gates).
    // Warp w handles local rows lr = 6w..6w+5; lane l holds cols [8l, 8l+8).
    float wr[6][8];
    float br[6];
    #pragma unroll
    for (int i = 0; i < 6; i++) {
        int lr = w * 6 + i;
        int grow = (lr >> 5) * HID + (int)rank * 32 + (lr & 31);
        br[i] = b_hh[grow];
        #pragma unroll
        for (int u = 0; u < 8; u++) wr[i][u] = W_hh[(size_t)grow * HID + l * 8 + u];
    }

    if (tid < HID) h_s[0][tid] = 0.f;
    int gcol = (tid >> 5) * HID + (int)rank * 32 + (tid & 31);  // valid for tid<96
    if (tid < 96) {
        gi_s[0][tid] = gi[gcol];
        gi_s[1][tid] = gi[H3 + gcol];
    }
    __syncthreads();
    cluster_sync_();

    for (int t = 0; t < SEQ; t++) {
        int p = t & 1;
        // --- phase A: 96 row-dot-products, plus gi prefetch (2 steps ahead) ---
        float4 h4a = *(const float4*)&h_s[p][l * 8];
        float4 h4b = *(const float4*)&h_s[p][l * 8 + 4];
        float hv[8] = {h4a.x, h4a.y, h4a.z, h4a.w, h4b.x, h4b.y, h4b.z, h4b.w};

        float gir = 0.f, giz = 0.f, gin = 0.f;
        if (tid < 32) {
            gir = gi_s[p][tid];
            giz = gi_s[p][32 + tid];
            gin = gi_s[p][64 + tid];
        }
        float pref = 0.f;
        bool do_pref = (tid < 96) && (t + 2 < SEQ);
        if (do_pref) pref = __ldg(&gi[(size_t)(t + 2) * H3 + gcol]);

        #pragma unroll
        for (int i = 0; i < 6; i++) {
            float s = wr[i][0] * hv[0];
            #pragma unroll
            for (int u = 1; u < 8; u++) s += wr[i][u] * hv[u];
            #pragma unroll
            for (int o = 16; o > 0; o >>= 1) s += __shfl_xor_sync(0xffffffffu, s, o);
            if (l == 0) gh_s[w * 6 + i] = s + br[i];
        }
        __syncthreads();
        if (do_pref) gi_s[p][tid] = pref;

        // --- phase B: gates + broadcast new h slice to all 8 CTAs ---
        if (tid < 32) {
            float r = 1.f / (1.f + __expf(-(gir + gh_s[tid])));
            float z = 1.f / (1.f + __expf(-(giz + gh_s[32 + tid])));
            float n = tanhf(gin + r * gh_s[64 + tid]);
            float hold = h_s[p][(int)rank * 32 + tid];
            float hnew = (1.f - z) * n + z * hold;
            uint32_t laddr = smem_u32_(&h_s[p ^ 1][(int)rank * 32 + tid]);
            #pragma unroll
            for (int c = 0; c < 8; c++) {
                uint32_t raddr;
                asm volatile("mapa.shared::cluster.u32 %0, %1, %2;"
                             : "=r"(raddr) : "r"(laddr), "r"(c));
                asm volatile("st.shared::cluster.f32 [%0], %1;"
                             :: "r"(raddr), "f"(hnew) : "memory");
            }
        }
        cluster_sync_();
    }

    // final h is in h_s[0] (4096 even). Reference returns (out, out): fill out_size.
    if (rank == 0) {
        for (int i = tid; i < out_size; i += 512) out[i] = h_s[0][i & (HID - 1)];
    }
}

// ---------------- host launch ----------------
extern "C" void kernel_launch(void* const* d_in, const int* in_sizes, int n_in,
                              void* d_out, int out_size) {
    const int*   tokens = (const int*)d_in[0];
    const float* emb = (const float*)d_in[1];
    const float* Wq  = (const float*)d_in[2];
    const float* bq  = (const float*)d_in[3];
    const float* Wk  = (const float*)d_in[4];
    const float* bk  = (const float*)d_in[5];
    const float* Wv  = (const float*)d_in[6];
    const float* bv  = (const float*)d_in[7];
    const float* Wo  = (const float*)d_in[8];
    const float* bo  = (const float*)d_in[9];
    const float* lng = (const float*)d_in[10];
    const float* lnb = (const float*)d_in[11];
    const float* Wih = (const float*)d_in[12];
    const float* Whh = (const float*)d_in[13];
    const float* bih = (const float*)d_in[14];
    const float* bhh = (const float*)d_in[15];
    float* out = (float*)d_out;

    static float *px, *pq, *pk, *pv, *psc, *po, *pcat, *pp, *py, *pgi;
    static bool init = false;
    if (!init) {
        cudaGetSymbolAddress((void**)&px, g_x);
        cudaGetSymbolAddress((void**)&pq, g_q);
        cudaGetSymbolAddress((void**)&pk, g_k);
        cudaGetSymbolAddress((void**)&pv, g_v);
        cudaGetSymbolAddress((void**)&psc, g_sc);
        cudaGetSymbolAddress((void**)&po, g_o);
        cudaGetSymbolAddress((void**)&pcat, g_cat);
        cudaGetSymbolAddress((void**)&pp, g_p);
        cudaGetSymbolAddress((void**)&py, g_y);
        cudaGetSymbolAddress((void**)&pgi, g_gi);
        init = true;
    }

    dim3 blk(256);

    // 1. embedding
    k_embed<<<SEQ, HID>>>(tokens, emb);

    // 2. per-head q/k/v: [S,H] @ [H,H] + bias, batched over heads
    sgemm64<false, true><<<dim3(HID / 64, SEQ / 64, NHEAD), blk>>>(
        px, Wq, bq, pq, SEQ, HID, HID, 1.f, 0, (size_t)HID * HID, HID, (size_t)SEQ * HID);
    sgemm64<false, true><<<dim3(HID / 64, SEQ / 64, NHEAD), blk>>>(
        px, Wk, bk, pk, SEQ, HID, HID, 1.f, 0, (size_t)HID * HID, HID, (size_t)SEQ * HID);
    sgemm64<false, true><<<dim3(HID / 64, SEQ / 64, NHEAD), blk>>>(
        px, Wv, bv, pv, SEQ, HID, HID, 1.f, 0, (size_t)HID * HID, HID, (size_t)SEQ * HID);

    // 3. scores = q @ k^T / 16, batched over heads
    sgemm64<true, false><<<dim3(SEQ / 64, SEQ / 64, NHEAD), blk>>>(
        pq, pk, nullptr, psc, SEQ, SEQ, HID, 1.0f / 16.0f,
        (size_t)SEQ * HID, (size_t)SEQ * HID, 0, (size_t)SEQ * SEQ);

    // 4. softmax over last axis
    k_softmax<<<NHEAD * SEQ, 256>>>(psc);

    // 5. o = a @ v
    sgemm64<false, false><<<dim3(HID / 64, SEQ / 64, NHEAD), blk>>>(
        psc, pv, nullptr, po, SEQ, HID, SEQ, 1.f,
        (size_t)SEQ * SEQ, (size_t)SEQ * HID, 0, (size_t)SEQ * HID);

    // 6. concat heads + output projection (+bo)
    k_cat<<<NHEAD * SEQ, HID>>>();
    sgemm64<false, true><<<dim3(HID / 64, SEQ / 64, 1), blk>>>(
        pcat, Wo, bo, pp, SEQ, HID, NHEAD * HID, 1.f, 0, 0, 0, 0);

    // 7. residual + LayerNorm
    k_addln<<<SEQ, HID>>>(lng, lnb);

    // 8. gi = y @ W_ih^T + b_ih  (all timesteps in parallel)
    sgemm64<true, true><<<dim3(H3 / 64, SEQ / 64, 1), blk>>>(
        py, Wih, bih, pgi, SEQ, H3, HID, 1.f, 0, 0, 0, 0);

    // 9. sequential GRU (8-CTA cluster, register-resident W_hh)
    k_gru<<<8, 512>>>(pgi, Whh, bhh, out, out_size);
}

// round 10
// speedup vs baseline: 1.4177x; 1.4177x over previous
#include <cuda_runtime.h>
#include <cstdint>
#include <cstddef>

#define SEQ 4096
#define HID 256
#define NHEAD 6
#define H3 768

// ---------------- scratch (static device globals; no allocation) ----------------
__device__ float g_x[SEQ * HID];                       // embedded tokens
__device__ float g_q[NHEAD * SEQ * HID];
__device__ float g_k[NHEAD * SEQ * HID];
__device__ float g_v[NHEAD * SEQ * HID];
__device__ float g_sc[(size_t)NHEAD * SEQ * SEQ];      // attention scores (402 MB)
__device__ float g_cat[(size_t)SEQ * NHEAD * HID];     // AV output, head-concat layout
__device__ float g_p[SEQ * HID];                       // attn output proj
__device__ float g_y[SEQ * HID];                       // post-LayerNorm
__device__ float g_gi[SEQ * H3];                       // precomputed GRU input gates

// ---------------- embedding gather ----------------
__global__ void k_embed(const int* __restrict__ tok, const float* __restrict__ emb) {
    int s = blockIdx.x, t = threadIdx.x;
    g_x[s * HID + t] = emb[(size_t)tok[s] * HID + t];
}

// ---------------- 128x128x16 double-buffered SGEMM, 8x8 micro-tile ----------------
// C[m, n] (row stride ldc) = alpha * A@B(^T) (+ bias[n]); batched via blockIdx.z.
template <bool TB, bool HASBIAS>
__global__ void __launch_bounds__(256, 2)
sgemm128(const float* __restrict__ A, const float* __restrict__ B,
         const float* __restrict__ bias, float* __restrict__ C,
         int M, int N, int K, float alpha, int ldc,
         size_t aB, size_t bB, size_t biasB, size_t cB) {
    A += (size_t)blockIdx.z * aB;
    B += (size_t)blockIdx.z * bB;
    C += (size_t)blockIdx.z * cB;
    if (HASBIAS) bias += (size_t)blockIdx.z * biasB;

    __shared__ float As[2][16][132];
    __shared__ float Bs[2][16][132];

    int tid = threadIdx.x;
    int tx = tid & 15, ty = tid >> 4;
    int m0 = blockIdx.y * 128, n0 = blockIdx.x * 128;

    // global-load thread mapping
    int ar = tid >> 2, ac = tid & 3;    // A (and B when TB): 64 rows/iter x 4 k-chunks
    int br = tid >> 5, bc = tid & 31;   // B non-TB: 8 k-rows/iter x 32 n-chunks

    float4 pa[2], pb[2];

    #define LOAD_A(k0)                                                          \
        pa[0] = *(const float4*)&A[(size_t)(m0 + ar) * K + (k0) + ac * 4];      \
        pa[1] = *(const float4*)&A[(size_t)(m0 + ar + 64) * K + (k0) + ac * 4];
    #define LOAD_B(k0)                                                          \
        if (TB) {                                                               \
            pb[0] = *(const float4*)&B[(size_t)(n0 + ar) * K + (k0) + ac * 4];  \
            pb[1] = *(const float4*)&B[(size_t)(n0 + ar + 64) * K + (k0) + ac * 4]; \
        } else {                                                                \
            pb[0] = *(const float4*)&B[(size_t)((k0) + br) * N + n0 + bc * 4];  \
            pb[1] = *(const float4*)&B[(size_t)((k0) + br + 8) * N + n0 + bc * 4]; \
        }
    #define STORE_AB(buf)                                                       \
        {                                                                       \
            float va0[4] = {pa[0].x, pa[0].y, pa[0].z, pa[0].w};                \
            float va1[4] = {pa[1].x, pa[1].y, pa[1].z, pa[1].w};                \
            _Pragma("unroll")                                                   \
            for (int j = 0; j < 4; j++) {                                       \
                As[buf][ac * 4 + j][ar] = va0[j];                               \
                As[buf][ac * 4 + j][ar + 64] = va1[j];                          \
            }                                                                   \
            if (TB) {                                                           \
                float vb0[4] = {pb[0].x, pb[0].y, pb[0].z, pb[0].w};            \
                float vb1[4] = {pb[1].x, pb[1].y, pb[1].z, pb[1].w};            \
                _Pragma("unroll")                                               \
                for (int j = 0; j < 4; j++) {                                   \
                    Bs[buf][ac * 4 + j][ar] = vb0[j];                           \
                    Bs[buf][ac * 4 + j][ar + 64] = vb1[j];                      \
                }                                                               \
            } else {                                                            \
                *(float4*)&Bs[buf][br][bc * 4] = pb[0];                         \
                *(float4*)&Bs[buf][br + 8][bc * 4] = pb[1];                     \
            }                                                                   \
        }

    LOAD_A(0) LOAD_B(0)
    STORE_AB(0)
    __syncthreads();

    float acc[8][8] = {};
    int nk = K >> 4;
    for (int kt = 0; kt < nk; kt++) {
        int buf = kt & 1;
        if (kt + 1 < nk) { LOAD_A((kt + 1) * 16) LOAD_B((kt + 1) * 16) }
        #pragma unroll
        for (int kk = 0; kk < 16; kk++) {
            float4 a0 = *(const float4*)&As[buf][kk][ty * 4];
            float4 a1 = *(const float4*)&As[buf][kk][ty * 4 + 64];
            float4 b0 = *(const float4*)&Bs[buf][kk][tx * 4];
            float4 b1 = *(const float4*)&Bs[buf][kk][tx * 4 + 64];
            float av[8] = {a0.x, a0.y, a0.z, a0.w, a1.x, a1.y, a1.z, a1.w};
            float bv[8] = {b0.x, b0.y, b0.z, b0.w, b1.x, b1.y, b1.z, b1.w};
            #pragma unroll
            for (int i = 0; i < 8; i++)
                #pragma unroll
                for (int j = 0; j < 8; j++) acc[i][j] += av[i] * bv[j];
        }
        if (kt + 1 < nk) STORE_AB(buf ^ 1)
        __syncthreads();
    }

    // epilogue: 4 float4 stores per row-group
    #pragma unroll
    for (int i = 0; i < 8; i++) {
        int m = m0 + ((i < 4) ? (ty * 4 + i) : (64 + ty * 4 + i - 4));
        #pragma unroll
        for (int jg = 0; jg < 2; jg++) {
            int n = n0 + tx * 4 + jg * 64;
            float4 r;
            r.x = acc[i][jg * 4 + 0] * alpha;
            r.y = acc[i][jg * 4 + 1] * alpha;
            r.z = acc[i][jg * 4 + 2] * alpha;
            r.w = acc[i][jg * 4 + 3] * alpha;
            if (HASBIAS) {
                float4 bb = *(const float4*)&bias[n];
                r.x += bb.x; r.y += bb.y; r.z += bb.z; r.w += bb.w;
            }
            *(float4*)&C[(size_t)m * ldc + n] = r;
        }
    }
    #undef LOAD_A
    #undef LOAD_B
    #undef STORE_AB
}

// ---------------- row softmax over 4096-length rows ----------------
__global__ void k_softmax(float* __restrict__ sc) {
    float* row = sc + (size_t)blockIdx.x * SEQ;
    int t = threadIdx.x;  // 256
    float v[16];
    float mx = -1e30f;
    #pragma unroll
    for (int i = 0; i < 16; i++) { v[i] = row[t + 256 * i]; mx = fmaxf(mx, v[i]); }
    __shared__ float red[256];
    red[t] = mx; __syncthreads();
    for (int s = 128; s > 0; s >>= 1) { if (t < s) red[t] = fmaxf(red[t], red[t + s]); __syncthreads(); }
    mx = red[0]; __syncthreads();
    float sum = 0.f;
    #pragma unroll
    for (int i = 0; i < 16; i++) { v[i] = __expf(v[i] - mx); sum += v[i]; }
    red[t] = sum; __syncthreads();
    for (int s = 128; s > 0; s >>= 1) { if (t < s) red[t] += red[t + s]; __syncthreads(); }
    float inv = 1.0f / red[0];
    #pragma unroll
    for (int i = 0; i < 16; i++) row[t + 256 * i] = v[i] * inv;
}

// ---------------- residual + LayerNorm ----------------
__global__ void k_addln(const float* __restrict__ g, const float* __restrict__ b) {
    int s = blockIdx.x, t = threadIdx.x;
    float v = g_x[s * HID + t] + g_p[s * HID + t];
    __shared__ float r1[256], r2[256];
    r1[t] = v; r2[t] = v * v; __syncthreads();
    for (int st = 128; st > 0; st >>= 1) {
        if (t < st) { r1[t] += r1[t + st]; r2[t] += r2[t + st]; }
        __syncthreads();
    }
    float mu = r1[0] * (1.0f / HID);
    float var = r2[0] * (1.0f / HID) - mu * mu;
    g_y[s * HID + t] = (v - mu) * rsqrtf(var + 1e-5f) * g[t] + b[t];
}

// ---------------- GRU: 8-CTA cluster, W_hh register-resident, st.async handoff ----------------
__device__ __forceinline__ void cluster_sync_() {
    asm volatile("barrier.cluster.arrive.aligned;" ::: "memory");
    asm volatile("barrier.cluster.wait.aligned;" ::: "memory");
}
__device__ __forceinline__ uint32_t smem_u32_(const void* p) {
    uint32_t a;
    asm("{ .reg .u64 t; cvta.to.shared.u64 t, %1; cvt.u32.u64 %0, t; }" : "=r"(a) : "l"(p));
    return a;
}
// remote store + tx-signal in one instruction (data+mbar must be same target CTA)
__device__ __forceinline__ void st_async_f32_(uint32_t ldata, uint32_t lmbar, float v, uint32_t cta) {
    uint32_t rd, rm;
    asm volatile("mapa.shared::cluster.u32 %0, %1, %2;" : "=r"(rd) : "r"(ldata), "r"(cta));
    asm volatile("mapa.shared::cluster.u32 %0, %1, %2;" : "=r"(rm) : "r"(lmbar), "r"(cta));
    asm volatile("st.async.shared::cluster.mbarrier::complete_tx::bytes.f32 [%0], %1, [%2];"
                 :: "r"(rd), "f"(v), "r"(rm) : "memory");
}
__device__ __forceinline__ void mbar_wait_cluster_(uint32_t mbar, uint32_t parity) {
    asm volatile(
        "{\n\t"
        ".reg .pred p;\n\t"
        "WAIT_%=:\n\t"
        "mbarrier.try_wait.parity.acquire.cluster.shared::cta.b64 p, [%0], %1, 0x989680;\n\t"
        "@p bra DONE_%=;\n\t"
        "bra WAIT_%=;\n\t"
        "DONE_%=:\n\t"
        "}"
        :: "r"(mbar), "r"(parity) : "memory");
}
__device__ __forceinline__ void mbar_expect_tx_(uint32_t mbar, uint32_t bytes) {
    asm volatile("mbarrier.arrive.expect_tx.shared.b64 _, [%0], %1;"
                 :: "r"(mbar), "r"(bytes) : "memory");
}

__global__ void __cluster_dims__(8, 1, 1) __launch_bounds__(512, 1)
k_gru(const float* __restrict__ gi, const float* __restrict__ W_hh,
      const float* __restrict__ b_hh, float* __restrict__ out, int out_size) {
    __shared__ __align__(16) float h_s[2][HID];
    __shared__ float gh_s[96];
    __shared__ float gi_s[2][96];
    __shared__ __align__(8) unsigned long long mbar[2];

    uint32_t rank;
    asm("mov.u32 %0, %%cluster_ctarank;" : "=r"(rank));
    int tid = threadIdx.x;
    int w = tid >> 5, l = tid & 31;

    // CTA `rank` owns h-dims [32*rank, 32*rank+32): 96 rows of W_hh (r,z,n gates).
    // Warp w handles local rows lr = 6w..6w+5; lane l holds cols [8l, 8l+8).
    float wr[6][8];
    float br[6];
    #pragma unroll
    for (int i = 0; i < 6; i++) {
        int lr = w * 6 + i;
        int grow = (lr >> 5) * HID + (int)rank * 32 + (lr & 31);
        br[i] = b_hh[grow];
        #pragma unroll
        for (int u = 0; u < 8; u++) wr[i][u] = W_hh[(size_t)grow * HID + l * 8 + u];
    }

    if (tid < HID) { h_s[0][tid] = 0.f; h_s[1][tid] = 0.f; }
    uint32_t mb_addr[2] = { smem_u32_(&mbar[0]), smem_u32_(&mbar[1]) };
    if (tid == 0) {
        asm volatile("mbarrier.init.shared.b64 [%0], 1;" :: "r"(mb_addr[0]) : "memory");
        asm volatile("mbarrier.init.shared.b64 [%0], 1;" :: "r"(mb_addr[1]) : "memory");
        asm volatile("fence.mbarrier_init.release.cluster;" ::: "memory");
        // pre-post first phase of both barriers (mbar[1]: step-0 stores,
        // mbar[0]: step-1 stores). All remote stores are gated by cluster_sync_.
        mbar_expect_tx_(mb_addr[1], 1024);
        mbar_expect_tx_(mb_addr[0], 1024);
    }
    int gcol = (tid >> 5) * HID + (int)rank * 32 + (tid & 31);  // valid for tid<96
    if (tid < 96) {
        gi_s[0][tid] = gi[gcol];
        gi_s[1][tid] = gi[H3 + gcol];
    }
    __syncthreads();
    cluster_sync_();   // mbarriers init'd + expect_tx posted, visible cluster-wide

    uint32_t par[2] = { 0u, 0u };

    for (int t = 0; t < SEQ; t++) {
        int b = t & 1;
        // wait for h(t) in buffer b (signaled by step t-1); step 0 reads the zeros
        if (t > 0) {
            mbar_wait_cluster_(mb_addr[b], par[b]);
            par[b] ^= 1u;
            // re-arm mbar[b] for its NEXT phase (signaled by step t+1 stores).
            // Ordering chain: this post -> __syncthreads below -> our step-t
            // stores -> remote step-(t+1) wait -> remote step-(t+1) stores.
            if (tid == 0) mbar_expect_tx_(mb_addr[b], 1024);
        }

        float4 h4a = *(const float4*)&h_s[b][l * 8];
        float4 h4b = *(const float4*)&h_s[b][l * 8 + 4];
        float hv[8] = {h4a.x, h4a.y, h4a.z, h4a.w, h4b.x, h4b.y, h4b.z, h4b.w};

        float gir = 0.f, giz = 0.f, gin = 0.f;
        if (tid < 32) {
            gir = gi_s[b][tid];
            giz = gi_s[b][32 + tid];
            gin = gi_s[b][64 + tid];
        }
        float pref = 0.f;
        bool do_pref = (tid < 96) && (t + 2 < SEQ);
        if (do_pref) pref = __ldg(&gi[(size_t)(t + 2) * H3 + gcol]);

        #pragma unroll
        for (int i = 0; i < 6; i++) {
            float s = wr[i][0] * hv[0];
            #pragma unroll
            for (int u = 1; u < 8; u++) s += wr[i][u] * hv[u];
            #pragma unroll
            for (int o = 16; o > 0; o >>= 1) s += __shfl_xor_sync(0xffffffffu, s, o);
            if (l == 0) gh_s[w * 6 + i] = s + br[i];
        }
        __syncthreads();   // publishes gh_s; orders expect_tx post before stores
        if (do_pref) gi_s[b][tid] = pref;

        if (tid < 32) {
            float r = 1.f / (1.f + __expf(-(gir + gh_s[tid])));
            float z = 1.f / (1.f + __expf(-(giz + gh_s[32 + tid])));
            float n = tanhf(gin + r * gh_s[64 + tid]);
            float hold = h_s[b][(int)rank * 32 + tid];
            float hnew = (1.f - z) * n + z * hold;
            uint32_t ldata = smem_u32_(&h_s[b ^ 1][(int)rank * 32 + tid]);
            #pragma unroll
            for (int c = 0; c < 8; c++) st_async_f32_(ldata, mb_addr[b ^ 1], hnew, (uint32_t)c);
        }
    }

    // final h(T) is in buffer 0 (signaled by step 4095 on mbar[0], parity 1);
    // every CTA waits so no CTA exits with inbound st.async still in flight.
    mbar_wait_cluster_(mb_addr[0], par[0]);
    if (rank == 0) {
        for (int i = tid; i < out_size; i += 512) out[i] = h_s[0][i & (HID - 1)];
    }
    cluster_sync_();
}

// ---------------- host launch ----------------
extern "C" void kernel_launch(void* const* d_in, const int* in_sizes, int n_in,
                              void* d_out, int out_size) {
    const int*   tokens = (const int*)d_in[0];
    const float* emb = (const float*)d_in[1];
    const float* Wq  = (const float*)d_in[2];
    const float* bq  = (const float*)d_in[3];
    const float* Wk  = (const float*)d_in[4];
    const float* bk  = (const float*)d_in[5];
    const float* Wv  = (const float*)d_in[6];
    const float* bv  = (const float*)d_in[7];
    const float* Wo  = (const float*)d_in[8];
    const float* bo  = (const float*)d_in[9];
    const float* lng = (const float*)d_in[10];
    const float* lnb = (const float*)d_in[11];
    const float* Wih = (const float*)d_in[12];
    const float* Whh = (const float*)d_in[13];
    const float* bih = (const float*)d_in[14];
    const float* bhh = (const float*)d_in[15];
    float* out = (float*)d_out;

    static float *px, *pq, *pk, *pv, *psc, *pcat, *pp, *py, *pgi;
    static bool init = false;
    if (!init) {
        cudaGetSymbolAddress((void**)&px, g_x);
        cudaGetSymbolAddress((void**)&pq, g_q);
        cudaGetSymbolAddress((void**)&pk, g_k);
        cudaGetSymbolAddress((void**)&pv, g_v);
        cudaGetSymbolAddress((void**)&psc, g_sc);
        cudaGetSymbolAddress((void**)&pcat, g_cat);
        cudaGetSymbolAddress((void**)&pp, g_p);
        cudaGetSymbolAddress((void**)&py, g_y);
        cudaGetSymbolAddress((void**)&pgi, g_gi);
        init = true;
    }

    dim3 blk(256);

    // 1. embedding
    k_embed<<<SEQ, HID>>>(tokens, emb);

    // 2. per-head q/k/v: [S,H] @ [H,H] + bias, batched over heads
    sgemm128<false, true><<<dim3(HID / 128, SEQ / 128, NHEAD), blk>>>(
        px, Wq, bq, pq, SEQ, HID, HID, 1.f, HID,
        0, (size_t)HID * HID, HID, (size_t)SEQ * HID);
    sgemm128<false, true><<<dim3(HID / 128, SEQ / 128, NHEAD), blk>>>(
        px, Wk, bk, pk, SEQ, HID, HID, 1.f, HID,
        0, (size_t)HID * HID, HID, (size_t)SEQ * HID);
    sgemm128<false, true><<<dim3(HID / 128, SEQ / 128, NHEAD), blk>>>(
        px, Wv, bv, pv, SEQ, HID, HID, 1.f, HID,
        0, (size_t)HID * HID, HID, (size_t)SEQ * HID);

    // 3. scores = q @ k^T / 16, batched over heads
    sgemm128<true, false><<<dim3(SEQ / 128, SEQ / 128, NHEAD), blk>>>(
        pq, pk, nullptr, psc, SEQ, SEQ, HID, 1.0f / 16.0f, SEQ,
        (size_t)SEQ * HID, (size_t)SEQ * HID, 0, (size_t)SEQ * SEQ);

    // 4. softmax over last axis
    k_softmax<<<NHEAD * SEQ, 256>>>(psc);

    // 5. o = a @ v, written directly in head-concat layout: cat[s, h*HID + e]
    sgemm128<false, false><<<dim3(HID / 128, SEQ / 128, NHEAD), blk>>>(
        psc, pv, nullptr, pcat, SEQ, HID, SEQ, 1.f, NHEAD * HID,
        (size_t)SEQ * SEQ, (size_t)SEQ * HID, 0, (size_t)HID);

    // 6. output projection (+bo)
    sgemm128<false, true><<<dim3(HID / 128, SEQ / 128, 1), blk>>>(
        pcat, Wo, bo, pp, SEQ, HID, NHEAD * HID, 1.f, HID, 0, 0, 0, 0);

    // 7. residual + LayerNorm
    k_addln<<<SEQ, HID>>>(lng, lnb);

    // 8. gi = y @ W_ih^T + b_ih  (all timesteps in parallel)
    sgemm128<true, true><<<dim3(H3 / 128, SEQ / 128, 1), blk>>>(
        py, Wih, bih, pgi, SEQ, H3, HID, 1.f, H3, 0, 0, 0, 0);

    // 9. sequential GRU (8-CTA cluster, register-resident W_hh, st.async handoff)
    k_gru<<<8, 512>>>(pgi, Whh, bhh, out, out_size);
}

// round 11
// speedup vs baseline: 1.7131x; 1.2084x over previous
#include <cuda_runtime.h>
#include <cstdint>
#include <cstddef>

#define SEQ 4096
#define HID 256
#define NHEAD 6
#define H3 768

// ---------------- scratch (static device globals; no allocation) ----------------
__device__ float g_x[SEQ * HID];                       // embedded tokens
__device__ float g_q[NHEAD * SEQ * HID];
__device__ float g_k[NHEAD * SEQ * HID];
__device__ float g_v[NHEAD * SEQ * HID];
__device__ float g_vt[NHEAD * HID * SEQ];              // v transposed: [h][e][t]
__device__ float g_sc[(size_t)NHEAD * SEQ * SEQ];      // attention scores (402 MB)
__device__ float g_cat[(size_t)SEQ * NHEAD * HID];     // AV output, head-concat layout
__device__ float g_p[SEQ * HID];                       // attn output proj
__device__ float g_y[SEQ * HID];                       // post-LayerNorm
__device__ float g_gi[SEQ * H3];                       // precomputed GRU input gates

// ---------------- embedding gather ----------------
__global__ void k_embed(const int* __restrict__ tok, const float* __restrict__ emb) {
    int s = blockIdx.x, t = threadIdx.x;
    g_x[s * HID + t] = emb[(size_t)tok[s] * HID + t];
}

// ---------------- 128x128x16 double-buffered SGEMM, 8x8 micro-tile (fp32 paths) ----
template <bool TB, bool HASBIAS>
__global__ void __launch_bounds__(256, 2)
sgemm128(const float* __restrict__ A, const float* __restrict__ B,
         const float* __restrict__ bias, float* __restrict__ C,
         int M, int N, int K, float alpha, int ldc,
         size_t aB, size_t bB, size_t biasB, size_t cB) {
    A += (size_t)blockIdx.z * aB;
    B += (size_t)blockIdx.z * bB;
    C += (size_t)blockIdx.z * cB;
    if (HASBIAS) bias += (size_t)blockIdx.z * biasB;

    __shared__ float As[2][16][132];
    __shared__ float Bs[2][16][132];

    int tid = threadIdx.x;
    int tx = tid & 15, ty = tid >> 4;
    int m0 = blockIdx.y * 128, n0 = blockIdx.x * 128;

    int ar = tid >> 2, ac = tid & 3;
    int br = tid >> 5, bc = tid & 31;

    float4 pa[2], pb[2];

    #define LOAD_A(k0)                                                          \
        pa[0] = *(const float4*)&A[(size_t)(m0 + ar) * K + (k0) + ac * 4];      \
        pa[1] = *(const float4*)&A[(size_t)(m0 + ar + 64) * K + (k0) + ac * 4];
    #define LOAD_B(k0)                                                          \
        if (TB) {                                                               \
            pb[0] = *(const float4*)&B[(size_t)(n0 + ar) * K + (k0) + ac * 4];  \
            pb[1] = *(const float4*)&B[(size_t)(n0 + ar + 64) * K + (k0) + ac * 4]; \
        } else {                                                                \
            pb[0] = *(const float4*)&B[(size_t)((k0) + br) * N + n0 + bc * 4];  \
            pb[1] = *(const float4*)&B[(size_t)((k0) + br + 8) * N + n0 + bc * 4]; \
        }
    #define STORE_AB(buf)                                                       \
        {                                                                       \
            float va0[4] = {pa[0].x, pa[0].y, pa[0].z, pa[0].w};                \
            float va1[4] = {pa[1].x, pa[1].y, pa[1].z, pa[1].w};                \
            _Pragma("unroll")                                                   \
            for (int j = 0; j < 4; j++) {                                       \
                As[buf][ac * 4 + j][ar] = va0[j];                               \
                As[buf][ac * 4 + j][ar + 64] = va1[j];                          \
            }                                                                   \
            if (TB) {                                                           \
                float vb0[4] = {pb[0].x, pb[0].y, pb[0].z, pb[0].w};            \
                float vb1[4] = {pb[1].x, pb[1].y, pb[1].z, pb[1].w};            \
                _Pragma("unroll")                                               \
                for (int j = 0; j < 4; j++) {                                   \
                    Bs[buf][ac * 4 + j][ar] = vb0[j];                           \
                    Bs[buf][ac * 4 + j][ar + 64] = vb1[j];                      \
                }                                                               \
            } else {                                                            \
                *(float4*)&Bs[buf][br][bc * 4] = pb[0];                         \
                *(float4*)&Bs[buf][br + 8][bc * 4] = pb[1];                     \
            }                                                                   \
        }

    LOAD_A(0) LOAD_B(0)
    STORE_AB(0)
    __syncthreads();

    float acc[8][8] = {};
    int nk = K >> 4;
    for (int kt = 0; kt < nk; kt++) {
        int buf = kt & 1;
        if (kt + 1 < nk) { LOAD_A((kt + 1) * 16) LOAD_B((kt + 1) * 16) }
        #pragma unroll
        for (int kk = 0; kk < 16; kk++) {
            float4 a0 = *(const float4*)&As[buf][kk][ty * 4];
            float4 a1 = *(const float4*)&As[buf][kk][ty * 4 + 64];
            float4 b0 = *(const float4*)&Bs[buf][kk][tx * 4];
            float4 b1 = *(const float4*)&Bs[buf][kk][tx * 4 + 64];
            float av[8] = {a0.x, a0.y, a0.z, a0.w, a1.x, a1.y, a1.z, a1.w};
            float bv[8] = {b0.x, b0.y, b0.z, b0.w, b1.x, b1.y, b1.z, b1.w};
            #pragma unroll
            for (int i = 0; i < 8; i++)
                #pragma unroll
                for (int j = 0; j < 8; j++) acc[i][j] += av[i] * bv[j];
        }
        if (kt + 1 < nk) STORE_AB(buf ^ 1)
        __syncthreads();
    }

    #pragma unroll
    for (int i = 0; i < 8; i++) {
        int m = m0 + ((i < 4) ? (ty * 4 + i) : (64 + ty * 4 + i - 4));
        #pragma unroll
        for (int jg = 0; jg < 2; jg++) {
            int n = n0 + tx * 4 + jg * 64;
            float4 r;
            r.x = acc[i][jg * 4 + 0] * alpha;
            r.y = acc[i][jg * 4 + 1] * alpha;
            r.z = acc[i][jg * 4 + 2] * alpha;
            r.w = acc[i][jg * 4 + 3] * alpha;
            if (HASBIAS) {
                float4 bb = *(const float4*)&bias[n];
                r.x += bb.x; r.y += bb.y; r.z += bb.z; r.w += bb.w;
            }
            *(float4*)&C[(size_t)m * ldc + n] = r;
        }
    }
    #undef LOAD_A
    #undef LOAD_B
    #undef STORE_AB
}

// ---------------- TF32 tensor-core GEMM: C = alpha * A @ Bt^T ----------------
// A: [M][K] row-major; Bt: [N][K] row-major (i.e. B already transposed).
// Block tile 128x128, warp tile 64x32 (2x4 warps), K-step 16, mma m16n8k8 tf32.
__device__ __forceinline__ uint32_t f2tf32_(float x) {
    uint32_t u;
    asm("cvt.rna.tf32.f32 %0, %1;" : "=r"(u) : "f"(x));
    return u;
}

__global__ void __launch_bounds__(256)
tmma128(const float* __restrict__ A, const float* __restrict__ Bt,
        float* __restrict__ C, int M, int N, int K, float alpha, int ldc,
        size_t aB, size_t bB, size_t cB) {
    A  += (size_t)blockIdx.z * aB;
    Bt += (size_t)blockIdx.z * bB;
    C  += (size_t)blockIdx.z * cB;

    // pad 20: fragment LDS bank = (20*g + tg) % 32 = (4g + tg) -> conflict-free
    __shared__ float As[2][128][20];
    __shared__ float Bs[2][128][20];

    int tid = threadIdx.x;
    int warp = tid >> 5, lane = tid & 31;
    int g = lane >> 2, tg = lane & 3;
    int wm = (warp & 1) * 64, wn = (warp >> 1) * 32;
    int m0 = blockIdx.y * 128, n0 = blockIdx.x * 128;

    // loader: 2 float4 per thread per array per tile (128 rows x 16 k)
    int lr0 = tid >> 2, lc = (tid & 3) * 4;           // f = 0*256+tid
    int lr1 = (256 + tid) >> 2;                        // f = 1*256+tid (same lc)

    float4 ra[2], rb[2];
    #define TLOAD(k0)                                                      \
        ra[0] = *(const float4*)&A[(size_t)(m0 + lr0) * K + (k0) + lc];    \
        ra[1] = *(const float4*)&A[(size_t)(m0 + lr1) * K + (k0) + lc];    \
        rb[0] = *(const float4*)&Bt[(size_t)(n0 + lr0) * K + (k0) + lc];   \
        rb[1] = *(const float4*)&Bt[(size_t)(n0 + lr1) * K + (k0) + lc];
    #define TSTORE(buf)                                                    \
        {                                                                  \
            uint32_t* pa0 = (uint32_t*)&As[buf][lr0][lc];                  \
            uint32_t* pa1 = (uint32_t*)&As[buf][lr1][lc];                  \
            uint32_t* pb0 = (uint32_t*)&Bs[buf][lr0][lc];                  \
            uint32_t* pb1 = (uint32_t*)&Bs[buf][lr1][lc];                  \
            pa0[0] = f2tf32_(ra[0].x); pa0[1] = f2tf32_(ra[0].y);          \
            pa0[2] = f2tf32_(ra[0].z); pa0[3] = f2tf32_(ra[0].w);          \
            pa1[0] = f2tf32_(ra[1].x); pa1[1] = f2tf32_(ra[1].y);          \
            pa1[2] = f2tf32_(ra[1].z); pa1[3] = f2tf32_(ra[1].w);          \
            pb0[0] = f2tf32_(rb[0].x); pb0[1] = f2tf32_(rb[0].y);          \
            pb0[2] = f2tf32_(rb[0].z); pb0[3] = f2tf32_(rb[0].w);          \
            pb1[0] = f2tf32_(rb[1].x); pb1[1] = f2tf32_(rb[1].y);          \
            pb1[2] = f2tf32_(rb[1].z); pb1[3] = f2tf32_(rb[1].w);          \
        }

    TLOAD(0)
    TSTORE(0)
    __syncthreads();

    float cc[4][4][4];
    #pragma unroll
    for (int i = 0; i < 4; i++)
        #pragma unroll
        for (int j = 0; j < 4; j++)
            #pragma unroll
            for (int r = 0; r < 4; r++) cc[i][j][r] = 0.f;

    int nk = K >> 4;
    for (int kt = 0; kt < nk; kt++) {
        int buf = kt & 1;
        if (kt + 1 < nk) TLOAD((kt + 1) * 16)
        #pragma unroll
        for (int ks = 0; ks < 2; ks++) {
            int k8 = ks * 8;
            uint32_t af[4][4], bf[4][2];
            #pragma unroll
            for (int mt = 0; mt < 4; mt++) {
                const float* base = &As[buf][wm + mt * 16][0];
                af[mt][0] = __float_as_uint(base[(g) * 20 + k8 + tg]);
                af[mt][1] = __float_as_uint(base[(g + 8) * 20 + k8 + tg]);
                af[mt][2] = __float_as_uint(base[(g) * 20 + k8 + tg + 4]);
                af[mt][3] = __float_as_uint(base[(g + 8) * 20 + k8 + tg + 4]);
            }
            #pragma unroll
            for (int nt = 0; nt < 4; nt++) {
                const float* base = &Bs[buf][wn + nt * 8][0];
                bf[nt][0] = __float_as_uint(base[g * 20 + k8 + tg]);
                bf[nt][1] = __float_as_uint(base[g * 20 + k8 + tg + 4]);
            }
            #pragma unroll
            for (int mt = 0; mt < 4; mt++)
                #pragma unroll
                for (int nt = 0; nt < 4; nt++) {
                    asm volatile(
                        "mma.sync.aligned.m16n8k8.row.col.f32.tf32.tf32.f32 "
                        "{%0,%1,%2,%3}, {%4,%5,%6,%7}, {%8,%9}, {%0,%1,%2,%3};"
                        : "+f"(cc[mt][nt][0]), "+f"(cc[mt][nt][1]),
                          "+f"(cc[mt][nt][2]), "+f"(cc[mt][nt][3])
                        : "r"(af[mt][0]), "r"(af[mt][1]), "r"(af[mt][2]), "r"(af[mt][3]),
                          "r"(bf[nt][0]), "r"(bf[nt][1]));
                }
        }
        if (kt + 1 < nk) TSTORE(buf ^ 1)
        __syncthreads();
    }

    // epilogue: c0=(g,2tg) c1=(g,2tg+1) c2=(g+8,2tg) c3=(g+8,2tg+1)
    #pragma unroll
    for (int mt = 0; mt < 4; mt++) {
        int rb_ = m0 + wm + mt * 16;
        #pragma unroll
        for (int nt = 0; nt < 4; nt++) {
            int cb = n0 + wn + nt * 8 + 2 * tg;
            float2 v01 = make_float2(cc[mt][nt][0] * alpha, cc[mt][nt][1] * alpha);
            float2 v23 = make_float2(cc[mt][nt][2] * alpha, cc[mt][nt][3] * alpha);
            *(float2*)&C[(size_t)(rb_ + g) * ldc + cb] = v01;
            *(float2*)&C[(size_t)(rb_ + g + 8) * ldc + cb] = v23;
        }
    }
    #undef TLOAD
    #undef TSTORE
}

// ---------------- v transpose: g_v[h][s][e] -> g_vt[h][e][s] ----------------
__global__ void k_transpose() {
    __shared__ float t[32][33];
    int h = blockIdx.z;
    int s0 = blockIdx.x * 32, e0 = blockIdx.y * 32;
    int x = threadIdx.x;
    const float* src = g_v + ((size_t)h * SEQ) * HID;
    float* dst = g_vt + ((size_t)h * HID) * SEQ;
    for (int j = threadIdx.y; j < 32; j += 8)
        t[j][x] = src[(size_t)(s0 + j) * HID + e0 + x];
    __syncthreads();
    for (int j = threadIdx.y; j < 32; j += 8)
        dst[(size_t)(e0 + j) * SEQ + s0 + x] = t[x][j];
}

// ---------------- row softmax over 4096-length rows ----------------
__global__ void k_softmax(float* __restrict__ sc) {
    float* row = sc + (size_t)blockIdx.x * SEQ;
    int t = threadIdx.x;  // 256
    float v[16];
    float mx = -1e30f;
    #pragma unroll
    for (int i = 0; i < 16; i++) { v[i] = row[t + 256 * i]; mx = fmaxf(mx, v[i]); }
    __shared__ float red[256];
    red[t] = mx; __syncthreads();
    for (int s = 128; s > 0; s >>= 1) { if (t < s) red[t] = fmaxf(red[t], red[t + s]); __syncthreads(); }
    mx = red[0]; __syncthreads();
    float sum = 0.f;
    #pragma unroll
    for (int i = 0; i < 16; i++) { v[i] = __expf(v[i] - mx); sum += v[i]; }
    red[t] = sum; __syncthreads();
    for (int s = 128; s > 0; s >>= 1) { if (t < s) red[t] += red[t + s]; __syncthreads(); }
    float inv = 1.0f / red[0];
    #pragma unroll
    for (int i = 0; i < 16; i++) row[t + 256 * i] = v[i] * inv;
}

// ---------------- residual + LayerNorm ----------------
__global__ void k_addln(const float* __restrict__ g, const float* __restrict__ b) {
    int s = blockIdx.x, t = threadIdx.x;
    float v = g_x[s * HID + t] + g_p[s * HID + t];
    __shared__ float r1[256], r2[256];
    r1[t] = v; r2[t] = v * v; __syncthreads();
    for (int st = 128; st > 0; st >>= 1) {
        if (t < st) { r1[t] += r1[t + st]; r2[t] += r2[t + st]; }
        __syncthreads();
    }
    float mu = r1[0] * (1.0f / HID);
    float var = r2[0] * (1.0f / HID) - mu * mu;
    g_y[s * HID + t] = (v - mu) * rsqrtf(var + 1e-5f) * g[t] + b[t];
}

// ---------------- GRU: 8-CTA cluster, W_hh register-resident, st.async handoff ----------------
__device__ __forceinline__ void cluster_sync_() {
    asm volatile("barrier.cluster.arrive.aligned;" ::: "memory");
    asm volatile("barrier.cluster.wait.aligned;" ::: "memory");
}
__device__ __forceinline__ uint32_t smem_u32_(const void* p) {
    uint32_t a;
    asm("{ .reg .u64 t; cvta.to.shared.u64 t, %1; cvt.u32.u64 %0, t; }" : "=r"(a) : "l"(p));
    return a;
}
__device__ __forceinline__ void st_async_f32_(uint32_t ldata, uint32_t lmbar, float v, uint32_t cta) {
    uint32_t rd, rm;
    asm volatile("mapa.shared::cluster.u32 %0, %1, %2;" : "=r"(rd) : "r"(ldata), "r"(cta));
    asm volatile("mapa.shared::cluster.u32 %0, %1, %2;" : "=r"(rm) : "r"(lmbar), "r"(cta));
    asm volatile("st.async.shared::cluster.mbarrier::complete_tx::bytes.f32 [%0], %1, [%2];"
                 :: "r"(rd), "f"(v), "r"(rm) : "memory");
}
__device__ __forceinline__ void mbar_wait_cluster_(uint32_t mbar, uint32_t parity) {
    asm volatile(
        "{\n\t"
        ".reg .pred p;\n\t"
        "WAIT_%=:\n\t"
        "mbarrier.try_wait.parity.acquire.cluster.shared::cta.b64 p, [%0], %1, 0x989680;\n\t"
        "@p bra DONE_%=;\n\t"
        "bra WAIT_%=;\n\t"
        "DONE_%=:\n\t"
        "}"
        :: "r"(mbar), "r"(parity) : "memory");
}
__device__ __forceinline__ void mbar_expect_tx_(uint32_t mbar, uint32_t bytes) {
    asm volatile("mbarrier.arrive.expect_tx.shared.b64 _, [%0], %1;"
                 :: "r"(mbar), "r"(bytes) : "memory");
}

__global__ void __cluster_dims__(8, 1, 1) __launch_bounds__(512, 1)
k_gru(const float* __restrict__ gi, const float* __restrict__ W_hh,
      const float* __restrict__ b_hh, float* __restrict__ out, int out_size) {
    __shared__ __align__(16) float h_s[2][HID];
    __shared__ float gh_s[96];
    __shared__ float gi_s[2][96];
    __shared__ __align__(8) unsigned long long mbar[2];

    uint32_t rank;
    asm("mov.u32 %0, %%cluster_ctarank;" : "=r"(rank));
    int tid = threadIdx.x;
    int w = tid >> 5, l = tid & 31;

    float wr[6][8];
    float br[6];
    #pragma unroll
    for (int i = 0; i < 6; i++) {
        int lr = w * 6 + i;
        int grow = (lr >> 5) * HID + (int)rank * 32 + (lr & 31);
        br[i] = b_hh[grow];
        #pragma unroll
        for (int u = 0; u < 8; u++) wr[i][u] = W_hh[(size_t)grow * HID + l * 8 + u];
    }

    if (tid < HID) { h_s[0][tid] = 0.f; h_s[1][tid] = 0.f; }
    uint32_t mb_addr[2] = { smem_u32_(&mbar[0]), smem_u32_(&mbar[1]) };
    if (tid == 0) {
        asm volatile("mbarrier.init.shared.b64 [%0], 1;" :: "r"(mb_addr[0]) : "memory");
        asm volatile("mbarrier.init.shared.b64 [%0], 1;" :: "r"(mb_addr[1]) : "memory");
        asm volatile("fence.mbarrier_init.release.cluster;" ::: "memory");
        mbar_expect_tx_(mb_addr[1], 1024);
        mbar_expect_tx_(mb_addr[0], 1024);
    }
    int gcol = (tid >> 5) * HID + (int)rank * 32 + (tid & 31);  // valid for tid<96
    if (tid < 96) {
        gi_s[0][tid] = gi[gcol];
        gi_s[1][tid] = gi[H3 + gcol];
    }
    __syncthreads();
    cluster_sync_();

    uint32_t par[2] = { 0u, 0u };

    for (int t = 0; t < SEQ; t++) {
        int b = t & 1;
        if (t > 0) {
            mbar_wait_cluster_(mb_addr[b], par[b]);
            par[b] ^= 1u;
            if (tid == 0) mbar_expect_tx_(mb_addr[b], 1024);
        }

        float4 h4a = *(const float4*)&h_s[b][l * 8];
        float4 h4b = *(const float4*)&h_s[b][l * 8 + 4];
        float hv[8] = {h4a.x, h4a.y, h4a.z, h4a.w, h4b.x, h4b.y, h4b.z, h4b.w};

        float gir = 0.f, giz = 0.f, gin = 0.f;
        if (tid < 32) {
            gir = gi_s[b][tid];
            giz = gi_s[b][32 + tid];
            gin = gi_s[b][64 + tid];
        }
        float pref = 0.f;
        bool do_pref = (tid < 96) && (t + 2 < SEQ);
        if (do_pref) pref = __ldg(&gi[(size_t)(t + 2) * H3 + gcol]);

        #pragma unroll
        for (int i = 0; i < 6; i++) {
            float s = wr[i][0] * hv[0];
            #pragma unroll
            for (int u = 1; u < 8; u++) s += wr[i][u] * hv[u];
            #pragma unroll
            for (int o = 16; o > 0; o >>= 1) s += __shfl_xor_sync(0xffffffffu, s, o);
            if (l == 0) gh_s[w * 6 + i] = s + br[i];
        }
        __syncthreads();
        if (do_pref) gi_s[b][tid] = pref;

        if (tid < 32) {
            float r = 1.f / (1.f + __expf(-(gir + gh_s[tid])));
            float z = 1.f / (1.f + __expf(-(giz + gh_s[32 + tid])));
            float n = tanhf(gin + r * gh_s[64 + tid]);
            float hold = h_s[b][(int)rank * 32 + tid];
            float hnew = (1.f - z) * n + z * hold;
            uint32_t ldata = smem_u32_(&h_s[b ^ 1][(int)rank * 32 + tid]);
            #pragma unroll
            for (int c = 0; c < 8; c++) st_async_f32_(ldata, mb_addr[b ^ 1], hnew, (uint32_t)c);
        }
    }

    mbar_wait_cluster_(mb_addr[0], par[0]);
    if (rank == 0) {
        for (int i = tid; i < out_size; i += 512) out[i] = h_s[0][i & (HID - 1)];
    }
    cluster_sync_();
}

// ---------------- host launch ----------------
extern "C" void kernel_launch(void* const* d_in, const int* in_sizes, int n_in,
                              void* d_out, int out_size) {
    const int*   tokens = (const int*)d_in[0];
    const float* emb = (const float*)d_in[1];
    const float* Wq  = (const float*)d_in[2];
    const float* bq  = (const float*)d_in[3];
    const float* Wk  = (const float*)d_in[4];
    const float* bk  = (const float*)d_in[5];
    const float* Wv  = (const float*)d_in[6];
    const float* bv  = (const float*)d_in[7];
    const float* Wo  = (const float*)d_in[8];
    const float* bo  = (const float*)d_in[9];
    const float* lng = (const float*)d_in[10];
    const float* lnb = (const float*)d_in[11];
    const float* Wih = (const float*)d_in[12];
    const float* Whh = (const float*)d_in[13];
    const float* bih = (const float*)d_in[14];
    const float* bhh = (const float*)d_in[15];
    float* out = (float*)d_out;

    static float *px, *pq, *pk, *pv, *pvt, *psc, *pcat, *pp, *py, *pgi;
    static bool init = false;
    if (!init) {
        cudaGetSymbolAddress((void**)&px, g_x);
        cudaGetSymbolAddress((void**)&pq, g_q);
        cudaGetSymbolAddress((void**)&pk, g_k);
        cudaGetSymbolAddress((void**)&pv, g_v);
        cudaGetSymbolAddress((void**)&pvt, g_vt);
        cudaGetSymbolAddress((void**)&psc, g_sc);
        cudaGetSymbolAddress((void**)&pcat, g_cat);
        cudaGetSymbolAddress((void**)&pp, g_p);
        cudaGetSymbolAddress((void**)&py, g_y);
        cudaGetSymbolAddress((void**)&pgi, g_gi);
        init = true;
    }

    dim3 blk(256);

    // 1. embedding
    k_embed<<<SEQ, HID>>>(tokens, emb);

    // 2. per-head q/k/v: [S,H] @ [H,H] + bias, batched over heads (fp32)
    sgemm128<false, true><<<dim3(HID / 128, SEQ / 128, NHEAD), blk>>>(
        px, Wq, bq, pq, SEQ, HID, HID, 1.f, HID,
        0, (size_t)HID * HID, HID, (size_t)SEQ * HID);
    sgemm128<false, true><<<dim3(HID / 128, SEQ / 128, NHEAD), blk>>>(
        px, Wk, bk, pk, SEQ, HID, HID, 1.f, HID,
        0, (size_t)HID * HID, HID, (size_t)SEQ * HID);
    sgemm128<false, true><<<dim3(HID / 128, SEQ / 128, NHEAD), blk>>>(
        px, Wv, bv, pv, SEQ, HID, HID, 1.f, HID,
        0, (size_t)HID * HID, HID, (size_t)SEQ * HID);

    // 2b. v transpose for tensor-core AV
    k_transpose<<<dim3(SEQ / 32, HID / 32, NHEAD), dim3(32, 8)>>>();

    // 3. scores = q @ k^T / 16 (tf32 tensor cores)
    tmma128<<<dim3(SEQ / 128, SEQ / 128, NHEAD), blk>>>(
        pq, pk, psc, SEQ, SEQ, HID, 1.0f / 16.0f, SEQ,
        (size_t)SEQ * HID, (size_t)SEQ * HID, (size_t)SEQ * SEQ);

    // 4. softmax over last axis
    k_softmax<<<NHEAD * SEQ, 256>>>(psc);

    // 5. o = a @ v (tf32 tensor cores), written in head-concat layout
    tmma128<<<dim3(HID / 128, SEQ / 128, NHEAD), blk>>>(
        psc, pvt, pcat, SEQ, HID, SEQ, 1.f, NHEAD * HID,
        (size_t)SEQ * SEQ, (size_t)HID * SEQ, (size_t)HID);

    // 6. output projection (+bo) (fp32)
    sgemm128<false, true><<<dim3(HID / 128, SEQ / 128, 1), blk>>>(
        pcat, Wo, bo, pp, SEQ, HID, NHEAD * HID, 1.f, HID, 0, 0, 0, 0);

    // 7. residual + LayerNorm
    k_addln<<<SEQ, HID>>>(lng, lnb);

    // 8. gi = y @ W_ih^T + b_ih (fp32)
    sgemm128<true, true><<<dim3(H3 / 128, SEQ / 128, 1), blk>>>(
        py, Wih, bih, pgi, SEQ, H3, HID, 1.f, H3, 0, 0, 0, 0);

    // 9. sequential GRU (8-CTA cluster, register-resident W_hh, st.async handoff)
    k_gru<<<8, 512>>>(pgi, Whh, bhh, out, out_size);
}